// round 10
// baseline (speedup 1.0000x reference)
#include <cuda_runtime.h>
#include <cuda_bf16.h>

// Quanvolutional layer: light-cone pruning + tan-factored RY gates.
// inputs:  (16, 3, 32, 32) float32
// weights: (16, 3, 16)     float32
// output:  (16, 16, 31, 31) float32  [B, O, Hp, Wp]
//
// RY(theta) = cos(theta/2) * [[1, -t], [t, 1]], t = tan(theta/2).
// Shear = 1 FMA per amplitude; scalar cos factors commute past CNOTs and
// fold into F = (prod cos)^2 applied once per (o, channel).

#define HP 31
#define WP 31
#define NPOS (16 * HP * WP)      // 15376 positions (b,h,w)
#define NPIX (16 * 3 * 32 * 32)  // 49152 input pixels

__device__ float2 g_wfuse[48 * 4];   // (cos,sin) half-angle of w0..w3 per (o,c)
__device__ float  g_wtan[48 * 16];   // tan(w_j/2) for j=4..15 per (o,c)
__device__ float  g_wF[48];          // (prod cos(w_j/2) over circuit's RY set)^2
__device__ float2 g_ptrig[NPIX];     // per-pixel (cos(x/2), sin(x/2))

// Heavy circuits first so the tail wave is made of cheap blocks.
__constant__ int c_omap[16] = {3, 8, 13, 4, 9, 14, 2, 7, 12, 0, 5, 10, 15, 1, 6, 11};
// Which weight indices are applied as tan-RYs per circuit class (o%5).
__constant__ unsigned c_tanmask[5] = {0x0010u, 0x0000u, 0x0010u, 0x9FF0u, 0x0FF0u};

__global__ __launch_bounds__(128) void trig_kernel(const float* __restrict__ w,
                                                   const float* __restrict__ in) {
    int idx = blockIdx.x * blockDim.x + threadIdx.x;  // 0..12287
    if (idx < 48) {  // one thread per (o, c) weight row
        int o = idx / 3;
        unsigned mask = c_tanmask[o % 5];
        float F = 1.0f;
        for (int j = 0; j < 16; j++) {
            float sn, cs;
            sincosf(0.5f * w[idx * 16 + j], &sn, &cs);
            if (j < 4) g_wfuse[idx * 4 + j] = make_float2(cs, sn);
            float csn = fabsf(cs) < 1e-20f ? (cs < 0.0f ? -1e-20f : 1e-20f) : cs;
            g_wtan[idx * 16 + j] = sn / csn;
            if (mask & (1u << j)) F *= csn * csn;
        }
        g_wF[idx] = F;
    }
    // One float4 (4 pixels) per thread; fast-path trig.
    float4 x = reinterpret_cast<const float4*>(in)[idx];
    float4 lo, hi;
    __sincosf(0.5f * x.x, &lo.y, &lo.x);
    __sincosf(0.5f * x.y, &lo.w, &lo.z);
    __sincosf(0.5f * x.z, &hi.y, &hi.x);
    __sincosf(0.5f * x.w, &hi.w, &hi.z);
    float4* outp = reinterpret_cast<float4*>(g_ptrig) + 2 * idx;
    outp[0] = lo;
    outp[1] = hi;
}

// Tan-form RY on wire W: s0' = s0 - t*s1 ; s1' = s1 + t*s0 (1 FMA each).
template <int W>
__device__ __forceinline__ void ryt(float s[16], float t) {
    constexpr int bit = 8 >> W;
#pragma unroll
    for (int i = 0; i < 16; i++) {
        if ((i & bit) == 0) {
            float a = s[i], b = s[i | bit];
            s[i]       = fmaf(-t, b, a);
            s[i | bit] = fmaf(t, a, b);
        }
    }
}

// CNOT: compile-time register permutation (zero SASS cost).
template <int C, int T>
__device__ __forceinline__ void cx(float s[16]) {
    constexpr int cb = 8 >> C, tb = 8 >> T;
#pragma unroll
    for (int i = 0; i < 16; i++) {
        if ((i & cb) && !(i & tb)) {
            float tmp = s[i]; s[i] = s[i | tb]; s[i | tb] = tmp;
        }
    }
}

// Angle addition: rotate pixel half-angle trig by weight half angle.
__device__ __forceinline__ float2 fuse(float2 x, float2 w) {
    return make_float2(x.x * w.x - x.y * w.y, x.y * w.x + x.x * w.y);
}

__device__ __forceinline__ void embed(float s[16], float2 a0, float2 a1,
                                      float2 a2, float2 a3) {
    float p01[4] = { a0.x * a1.x, a0.x * a1.y, a0.y * a1.x, a0.y * a1.y };
    float p23[4] = { a2.x * a3.x, a2.x * a3.y, a2.y * a3.x, a2.y * a3.y };
#pragma unroll
    for (int q = 0; q < 16; q++) s[q] = p01[q >> 2] * p23[q & 3];
}

// (sum_{wire0=0} s^2) - (sum_{wire0=1} s^2), unnormalized.
__device__ __forceinline__ float expz0(const float s[16]) {
    float ep = 0.0f, en = 0.0f;
#pragma unroll
    for (int q = 0; q < 16; q++) {
        if (q & 8) en = fmaf(s[q], s[q], en);
        else       ep = fmaf(s[q], s[q], ep);
    }
    return ep - en;
}

__global__ __launch_bounds__(128, 4) void quanv_kernel(float* __restrict__ out) {
    const int o = c_omap[blockIdx.y];
    __shared__ float2 wfu[3][4];
    __shared__ float  wtn[3][16];
    __shared__ float  wF[3];
    if (threadIdx.x < 48) {
        int c = threadIdx.x >> 4, j = threadIdx.x & 15;
        wtn[c][j] = g_wtan[(o * 3 + c) * 16 + j];
        if (j < 4) wfu[c][j] = g_wfuse[(o * 3 + c) * 4 + j];
        if (j == 0) wF[c] = g_wF[o * 3 + c];
    }
    __syncthreads();

    int p = blockIdx.x * blockDim.x + threadIdx.x;
    if (p >= NPOS) return;
    int b  = p / (HP * WP);
    int hw = p - b * (HP * WP);
    int h  = hw / WP;
    int w  = hw - h * WP;

    const int circ = o % 5;
    float acc = 0.0f;

#pragma unroll
    for (int c = 0; c < 3; c++) {
        const float2* tp = g_ptrig + (((b * 3 + c) * 32) + h) * 32 + w;
        const float2* WU = wfu[c];
        const float*  T  = wtn[c];
        const float   F  = wF[c];

        switch (circ) {
            case 0: {  // ran -> wires {0,1}: fused ry0,ry1; cx01; tan-ry0(w4)
                float2 a0 = fuse(tp[0], WU[0]);
                float2 a1 = fuse(tp[1], WU[1]);
                float t4 = T[4];
                // product amps after CNOT(0,1)
                float t00 = a0.x * a1.x, t01 = a0.x * a1.y;
                float t10 = a0.y * a1.y, t11 = a0.y * a1.x;
                // tan-RY(w4) on wire 0
                float n00 = fmaf(-t4, t10, t00), n10 = fmaf(t4, t00, t10);
                float n01 = fmaf(-t4, t11, t01), n11 = fmaf(t4, t01, t11);
                float d = n00 * n00 + n01 * n01 - n10 * n10 - n11 * n11;
                acc = fmaf(F, d, acc);
                break;
            }
            case 1: {  // line -> single qubit: <Z0> = cos(x0 + w0)
                float2 a0 = fuse(tp[0], WU[0]);
                acc += a0.x * a0.x - a0.y * a0.y;   // F == 1
                break;
            }
            case 2: {  // ring -> fused embed, 4 CNOTs, tan-ry0(w4)
                float s[16];
                embed(s, fuse(tp[0], WU[0]), fuse(tp[1], WU[1]),
                         fuse(tp[32], WU[2]), fuse(tp[33], WU[3]));
                cx<0, 1>(s); cx<1, 2>(s); cx<2, 3>(s); cx<3, 0>(s);
                ryt<0>(s, T[4]);
                acc = fmaf(F, expz0(s), acc);
                break;
            }
            case 3: {  // doublering -> fused embed; 10 tan-RYs; pruned tail
                float s[16];
                embed(s, fuse(tp[0], WU[0]), fuse(tp[1], WU[1]),
                         fuse(tp[32], WU[2]), fuse(tp[33], WU[3]));
                cx<0, 1>(s); cx<1, 2>(s); cx<2, 3>(s); cx<3, 0>(s);
                ryt<0>(s, T[4]); ryt<1>(s, T[5]); ryt<2>(s, T[6]); ryt<3>(s, T[7]);
                cx<3, 0>(s); cx<2, 3>(s); cx<1, 2>(s); cx<0, 1>(s);
                ryt<0>(s, T[8]); ryt<1>(s, T[9]); ryt<2>(s, T[10]); ryt<3>(s, T[11]);
                cx<0, 1>(s); cx<1, 2>(s); cx<2, 3>(s); cx<3, 0>(s);
                ryt<0>(s, T[12]);   // ry1(w13), ry2(w14) pruned
                ryt<3>(s, T[15]);
                cx<3, 0>(s);        // trailing cx23,cx12,cx01 pruned
                acc = fmaf(F, expz0(s), acc);
                break;
            }
            default: {  // blockring -> fused embed; 8 tan-RYs
                float s[16];
                embed(s, fuse(tp[0], WU[0]), fuse(tp[1], WU[1]),
                         fuse(tp[32], WU[2]), fuse(tp[33], WU[3]));
                cx<0, 1>(s); cx<2, 3>(s); cx<1, 2>(s); cx<3, 0>(s);
                ryt<0>(s, T[4]); ryt<1>(s, T[5]); ryt<2>(s, T[6]); ryt<3>(s, T[7]);
                cx<0, 1>(s); cx<2, 3>(s); cx<1, 2>(s); cx<3, 0>(s);
                ryt<0>(s, T[8]); ryt<1>(s, T[9]); ryt<2>(s, T[10]); ryt<3>(s, T[11]);
                cx<0, 1>(s); cx<2, 3>(s); cx<1, 2>(s); cx<3, 0>(s);
                acc = fmaf(F, expz0(s), acc);
                break;
            }
        }
    }

    out[((b * 16 + o) * HP + h) * WP + w] = acc;
}

extern "C" void kernel_launch(void* const* d_in, const int* in_sizes, int n_in,
                              void* d_out, int out_size) {
    const float* in = (const float*)d_in[0];   // (16,3,32,32)
    const float* w  = (const float*)d_in[1];   // (16,3,16)
    float* out = (float*)d_out;                // (16,16,31,31)

    trig_kernel<<<96, 128>>>(w, in);           // 12288 threads = NPIX/4

    dim3 grid((NPOS + 127) / 128, 16);
    quanv_kernel<<<grid, 128>>>(out);
}

// round 12
// speedup vs baseline: 1.1278x; 1.1278x over previous
#include <cuda_runtime.h>
#include <cuda_bf16.h>

// Quanvolutional layer: light-cone pruning + tan-factored RY gates.
// inputs:  (16, 3, 32, 32) float32
// weights: (16, 3, 16)     float32
// output:  (16, 16, 31, 31) float32  [B, O, Hp, Wp]
//
// RY(theta) = cos(theta/2) * [[1, -t], [t, 1]], t = tan(theta/2).
// Shear = 1 FMA per amplitude; scalar cos factors fold into F = (prod cos)^2
// applied once per (o, channel).

#define HP 31
#define WP 31
#define NPOS (16 * HP * WP)      // 15376 positions (b,h,w)
#define NPIX (16 * 3 * 32 * 32)  // 49152 input pixels

__device__ float2 g_wfuse[48 * 4];   // (cos,sin) half-angle of w0..w3 per (o,c)
__device__ float  g_wtan[48 * 16];   // tan(w_j/2) per (o,c)
__device__ float  g_wF[48];          // (prod cos(w_j/2) over circuit's tan-RY set)^2
__device__ float2 g_ptrig[NPIX];     // per-pixel (cos(x/2), sin(x/2))

// Heavy circuits first so the tail wave is made of cheap blocks.
__constant__ int c_omap[16] = {3, 8, 13, 4, 9, 14, 2, 7, 12, 0, 5, 10, 15, 1, 6, 11};
// Which weight indices are applied as tan-RYs per circuit class (o%5).
__constant__ unsigned c_tanmask[5] = {0x0010u, 0x0000u, 0x0010u, 0x9FF0u, 0x0FF0u};

__global__ __launch_bounds__(128) void trig_kernel(const float* __restrict__ w,
                                                   const float* __restrict__ in) {
    int idx = blockIdx.x * blockDim.x + threadIdx.x;  // 0..12287
    if (idx < 768) {  // one thread per weight element; 16-lane group = one (o,c) row
        int row = idx >> 4, j = idx & 15;  // row = o*3 + c
        float sn, cs;
        sincosf(0.5f * w[idx], &sn, &cs);
        if (j < 4) g_wfuse[row * 4 + j] = make_float2(cs, sn);
        float csn = fabsf(cs) < 1e-20f ? (cs < 0.0f ? -1e-20f : 1e-20f) : cs;
        g_wtan[idx] = sn / csn;
        unsigned mask = c_tanmask[(row / 3) % 5];
        float f = (mask >> j & 1u) ? csn * csn : 1.0f;
        // product over the 16-lane group (xor distances 1,2,4,8 stay in-group)
        #pragma unroll
        for (int d = 1; d < 16; d <<= 1)
            f *= __shfl_xor_sync(0xFFFFFFFFu, f, d);
        if (j == 0) g_wF[row] = f;
    }
    // One float4 (4 pixels) per thread; fast-path trig.
    float4 x = reinterpret_cast<const float4*>(in)[idx];
    float4 lo, hi;
    __sincosf(0.5f * x.x, &lo.y, &lo.x);
    __sincosf(0.5f * x.y, &lo.w, &lo.z);
    __sincosf(0.5f * x.z, &hi.y, &hi.x);
    __sincosf(0.5f * x.w, &hi.w, &hi.z);
    float4* outp = reinterpret_cast<float4*>(g_ptrig) + 2 * idx;
    outp[0] = lo;
    outp[1] = hi;
}

// Tan-form RY on wire W: s0' = s0 - t*s1 ; s1' = s1 + t*s0 (1 FMA each).
template <int W>
__device__ __forceinline__ void ryt(float s[16], float t) {
    constexpr int bit = 8 >> W;
#pragma unroll
    for (int i = 0; i < 16; i++) {
        if ((i & bit) == 0) {
            float a = s[i], b = s[i | bit];
            s[i]       = fmaf(-t, b, a);
            s[i | bit] = fmaf(t, a, b);
        }
    }
}

// CNOT: compile-time register permutation (zero SASS cost).
template <int C, int T>
__device__ __forceinline__ void cx(float s[16]) {
    constexpr int cb = 8 >> C, tb = 8 >> T;
#pragma unroll
    for (int i = 0; i < 16; i++) {
        if ((i & cb) && !(i & tb)) {
            float tmp = s[i]; s[i] = s[i | tb]; s[i | tb] = tmp;
        }
    }
}

// Angle addition: rotate pixel half-angle trig by weight half angle.
__device__ __forceinline__ float2 fuse(float2 x, float2 w) {
    return make_float2(x.x * w.x - x.y * w.y, x.y * w.x + x.x * w.y);
}

__device__ __forceinline__ void embed(float s[16], float2 a0, float2 a1,
                                      float2 a2, float2 a3) {
    float p01[4] = { a0.x * a1.x, a0.x * a1.y, a0.y * a1.x, a0.y * a1.y };
    float p23[4] = { a2.x * a3.x, a2.x * a3.y, a2.y * a3.x, a2.y * a3.y };
#pragma unroll
    for (int q = 0; q < 16; q++) s[q] = p01[q >> 2] * p23[q & 3];
}

// (sum_{wire0=0} s^2) - (sum_{wire0=1} s^2), unnormalized.
__device__ __forceinline__ float expz0(const float s[16]) {
    float ep = 0.0f, en = 0.0f;
#pragma unroll
    for (int q = 0; q < 16; q++) {
        if (q & 8) en = fmaf(s[q], s[q], en);
        else       ep = fmaf(s[q], s[q], ep);
    }
    return ep - en;
}

__global__ __launch_bounds__(128, 4) void quanv_kernel(float* __restrict__ out) {
    const int o = c_omap[blockIdx.y];
    __shared__ float2 wfu[3][4];
    __shared__ float  wtn[3][16];
    __shared__ float  wF[3];
    if (threadIdx.x < 48) {
        int c = threadIdx.x >> 4, j = threadIdx.x & 15;
        wtn[c][j] = g_wtan[(o * 3 + c) * 16 + j];
        if (j < 4) wfu[c][j] = g_wfuse[(o * 3 + c) * 4 + j];
        if (j == 0) wF[c] = g_wF[o * 3 + c];
    }
    __syncthreads();

    int p = blockIdx.x * blockDim.x + threadIdx.x;
    if (p >= NPOS) return;
    int b  = p / (HP * WP);
    int hw = p - b * (HP * WP);
    int h  = hw / WP;
    int w  = hw - h * WP;

    // Front-load ALL pixel trig (3 channels x 4 pixels, MLP=12) so the L2
    // latency is exposed once, not once per channel.
    float2 P[3][4];
    {
        const float2* base = g_ptrig + ((b * 3) * 32 + h) * 32 + w;
#pragma unroll
        for (int c = 0; c < 3; c++) {
            const float2* tp = base + c * 1024;
            P[c][0] = tp[0];  P[c][1] = tp[1];
            P[c][2] = tp[32]; P[c][3] = tp[33];
        }
    }

    const int circ = o % 5;
    float acc = 0.0f;

#pragma unroll
    for (int c = 0; c < 3; c++) {
        const float2* WU = wfu[c];
        const float*  T  = wtn[c];
        const float   F  = wF[c];

        switch (circ) {
            case 0: {  // ran -> wires {0,1}: fused ry0,ry1; cx01; tan-ry0(w4)
                float2 a0 = fuse(P[c][0], WU[0]);
                float2 a1 = fuse(P[c][1], WU[1]);
                float t4 = T[4];
                float t00 = a0.x * a1.x, t01 = a0.x * a1.y;
                float t10 = a0.y * a1.y, t11 = a0.y * a1.x;
                float n00 = fmaf(-t4, t10, t00), n10 = fmaf(t4, t00, t10);
                float n01 = fmaf(-t4, t11, t01), n11 = fmaf(t4, t01, t11);
                float d = n00 * n00 + n01 * n01 - n10 * n10 - n11 * n11;
                acc = fmaf(F, d, acc);
                break;
            }
            case 1: {  // line -> single qubit: <Z0> = cos(x0 + w0)
                float2 a0 = fuse(P[c][0], WU[0]);
                acc += a0.x * a0.x - a0.y * a0.y;   // F == 1
                break;
            }
            case 2: {  // ring -> fused embed, 4 CNOTs, tan-ry0(w4)
                float s[16];
                embed(s, fuse(P[c][0], WU[0]), fuse(P[c][1], WU[1]),
                         fuse(P[c][2], WU[2]), fuse(P[c][3], WU[3]));
                cx<0, 1>(s); cx<1, 2>(s); cx<2, 3>(s); cx<3, 0>(s);
                ryt<0>(s, T[4]);
                acc = fmaf(F, expz0(s), acc);
                break;
            }
            case 3: {  // doublering -> fused embed; 10 tan-RYs; pruned tail
                float s[16];
                embed(s, fuse(P[c][0], WU[0]), fuse(P[c][1], WU[1]),
                         fuse(P[c][2], WU[2]), fuse(P[c][3], WU[3]));
                cx<0, 1>(s); cx<1, 2>(s); cx<2, 3>(s); cx<3, 0>(s);
                ryt<0>(s, T[4]); ryt<1>(s, T[5]); ryt<2>(s, T[6]); ryt<3>(s, T[7]);
                cx<3, 0>(s); cx<2, 3>(s); cx<1, 2>(s); cx<0, 1>(s);
                ryt<0>(s, T[8]); ryt<1>(s, T[9]); ryt<2>(s, T[10]); ryt<3>(s, T[11]);
                cx<0, 1>(s); cx<1, 2>(s); cx<2, 3>(s); cx<3, 0>(s);
                ryt<0>(s, T[12]);   // ry1(w13), ry2(w14) pruned
                ryt<3>(s, T[15]);
                cx<3, 0>(s);        // trailing cx23,cx12,cx01 pruned
                acc = fmaf(F, expz0(s), acc);
                break;
            }
            default: {  // blockring -> fused embed; 8 tan-RYs
                float s[16];
                embed(s, fuse(P[c][0], WU[0]), fuse(P[c][1], WU[1]),
                         fuse(P[c][2], WU[2]), fuse(P[c][3], WU[3]));
                cx<0, 1>(s); cx<2, 3>(s); cx<1, 2>(s); cx<3, 0>(s);
                ryt<0>(s, T[4]); ryt<1>(s, T[5]); ryt<2>(s, T[6]); ryt<3>(s, T[7]);
                cx<0, 1>(s); cx<2, 3>(s); cx<1, 2>(s); cx<3, 0>(s);
                ryt<0>(s, T[8]); ryt<1>(s, T[9]); ryt<2>(s, T[10]); ryt<3>(s, T[11]);
                cx<0, 1>(s); cx<2, 3>(s); cx<1, 2>(s); cx<3, 0>(s);
                acc = fmaf(F, expz0(s), acc);
                break;
            }
        }
    }

    out[((b * 16 + o) * HP + h) * WP + w] = acc;
}

extern "C" void kernel_launch(void* const* d_in, const int* in_sizes, int n_in,
                              void* d_out, int out_size) {
    const float* in = (const float*)d_in[0];   // (16,3,32,32)
    const float* w  = (const float*)d_in[1];   // (16,3,16)
    float* out = (float*)d_out;                // (16,16,31,31)

    trig_kernel<<<96, 128>>>(w, in);           // 12288 threads = NPIX/4

    dim3 grid((NPOS + 127) / 128, 16);
    quanv_kernel<<<grid, 128>>>(out);
}

// round 15
// speedup vs baseline: 1.2966x; 1.1497x over previous
#include <cuda_runtime.h>
#include <cuda_bf16.h>

// Quanvolutional layer, single fused kernel.
// inputs:  (16, 3, 32, 32) float32
// weights: (16, 3, 16)     float32
// output:  (16, 16, 31, 31) float32  [B, O, Hp, Wp]
//
// Per block (one output channel o): preamble computes weight trig/tan/F in
// smem (48 threads, overlapped). Per thread: load 12 raw pixels, inline
// __sincosf (MUFU pipe, overlaps FMA stream), run pruned tan-RY circuits.

#define HP 31
#define WP 31
#define NPOS (16 * HP * WP)      // 15376 positions (b,h,w)

// Heavy circuits first so the tail wave is made of cheap blocks.
__constant__ int c_omap[16] = {3, 8, 13, 4, 9, 14, 2, 7, 12, 0, 5, 10, 15, 1, 6, 11};
// Which weight indices are applied as tan-RYs per circuit class (o%5).
__constant__ unsigned c_tanmask[5] = {0x0010u, 0x0000u, 0x0010u, 0x9FF0u, 0x0FF0u};

// Tan-form RY on wire W: s0' = s0 - t*s1 ; s1' = s1 + t*s0 (1 FMA each).
template <int W>
__device__ __forceinline__ void ryt(float s[16], float t) {
    constexpr int bit = 8 >> W;
#pragma unroll
    for (int i = 0; i < 16; i++) {
        if ((i & bit) == 0) {
            float a = s[i], b = s[i | bit];
            s[i]       = fmaf(-t, b, a);
            s[i | bit] = fmaf(t, a, b);
        }
    }
}

// CNOT: compile-time register permutation (zero SASS cost).
template <int C, int T>
__device__ __forceinline__ void cx(float s[16]) {
    constexpr int cb = 8 >> C, tb = 8 >> T;
#pragma unroll
    for (int i = 0; i < 16; i++) {
        if ((i & cb) && !(i & tb)) {
            float tmp = s[i]; s[i] = s[i | tb]; s[i | tb] = tmp;
        }
    }
}

// Half-angle trig of pixel x, rotated by weight half angle (angle addition).
__device__ __forceinline__ float2 trigfuse(float x, float2 w) {
    float sn, cs;
    __sincosf(0.5f * x, &sn, &cs);
    return make_float2(cs * w.x - sn * w.y, sn * w.x + cs * w.y);
}

__device__ __forceinline__ void embed(float s[16], float2 a0, float2 a1,
                                      float2 a2, float2 a3) {
    float p01[4] = { a0.x * a1.x, a0.x * a1.y, a0.y * a1.x, a0.y * a1.y };
    float p23[4] = { a2.x * a3.x, a2.x * a3.y, a2.y * a3.x, a2.y * a3.y };
#pragma unroll
    for (int q = 0; q < 16; q++) s[q] = p01[q >> 2] * p23[q & 3];
}

// (sum_{wire0=0} s^2) - (sum_{wire0=1} s^2), unnormalized.
__device__ __forceinline__ float expz0(const float s[16]) {
    float ep = 0.0f, en = 0.0f;
#pragma unroll
    for (int q = 0; q < 16; q++) {
        if (q & 8) en = fmaf(s[q], s[q], en);
        else       ep = fmaf(s[q], s[q], ep);
    }
    return ep - en;
}

__global__ __launch_bounds__(128, 4) void quanv_kernel(const float* __restrict__ in,
                                                       const float* __restrict__ wt,
                                                       float* __restrict__ out) {
    const int o = c_omap[blockIdx.y];
    const int circ = o % 5;

    // Block preamble: weight trig for this o's 3 channels (48 threads).
    __shared__ float2 wfu[3][4];   // (cos,sin) half-angle of w0..w3
    __shared__ float  wtn[3][16];  // tan(w_j/2)
    __shared__ float  wF[3];       // (prod cos over tan-RY set)^2
    if (threadIdx.x < 48) {
        int c = threadIdx.x >> 4, j = threadIdx.x & 15;
        float sn, cs;
        sincosf(0.5f * wt[(o * 3 + c) * 16 + j], &sn, &cs);
        if (j < 4) wfu[c][j] = make_float2(cs, sn);
        float csn = fabsf(cs) < 1e-20f ? (cs < 0.0f ? -1e-20f : 1e-20f) : cs;
        wtn[c][j] = sn / csn;
        unsigned mask = c_tanmask[circ];
        float f = (mask >> j & 1u) ? csn * csn : 1.0f;
        // product over the 16-lane group; lanes 32..47 are a half-warp.
        unsigned sm = (threadIdx.x < 32) ? 0xFFFFFFFFu : 0x0000FFFFu;
#pragma unroll
        for (int d = 1; d < 16; d <<= 1)
            f *= __shfl_xor_sync(sm, f, d);
        if (j == 0) wF[c] = f;
    }
    __syncthreads();

    int p = blockIdx.x * blockDim.x + threadIdx.x;
    if (p >= NPOS) return;
    int b  = p / (HP * WP);
    int hw = p - b * (HP * WP);
    int h  = hw / WP;
    int w  = hw - h * WP;

    // Front-load all 12 raw pixels (MLP=12, one latency exposure).
    float px[3][4];
    {
        const float* base = in + ((b * 3) * 32 + h) * 32 + w;
#pragma unroll
        for (int c = 0; c < 3; c++) {
            const float* ip = base + c * 1024;
            px[c][0] = ip[0];  px[c][1] = ip[1];
            px[c][2] = ip[32]; px[c][3] = ip[33];
        }
    }

    float acc = 0.0f;

#pragma unroll
    for (int c = 0; c < 3; c++) {
        const float2* WU = wfu[c];
        const float*  T  = wtn[c];
        const float   F  = wF[c];

        switch (circ) {
            case 0: {  // ran -> wires {0,1}: fused ry0,ry1; cx01; tan-ry0(w4)
                float2 a0 = trigfuse(px[c][0], WU[0]);
                float2 a1 = trigfuse(px[c][1], WU[1]);
                float t4 = T[4];
                float t00 = a0.x * a1.x, t01 = a0.x * a1.y;
                float t10 = a0.y * a1.y, t11 = a0.y * a1.x;
                float n00 = fmaf(-t4, t10, t00), n10 = fmaf(t4, t00, t10);
                float n01 = fmaf(-t4, t11, t01), n11 = fmaf(t4, t01, t11);
                float d = n00 * n00 + n01 * n01 - n10 * n10 - n11 * n11;
                acc = fmaf(F, d, acc);
                break;
            }
            case 1: {  // line -> single qubit: <Z0> = cos(x0 + w0)
                float2 a0 = trigfuse(px[c][0], WU[0]);
                acc += a0.x * a0.x - a0.y * a0.y;   // F == 1
                break;
            }
            case 2: {  // ring -> fused embed, 4 CNOTs, tan-ry0(w4)
                float s[16];
                embed(s, trigfuse(px[c][0], WU[0]), trigfuse(px[c][1], WU[1]),
                         trigfuse(px[c][2], WU[2]), trigfuse(px[c][3], WU[3]));
                cx<0, 1>(s); cx<1, 2>(s); cx<2, 3>(s); cx<3, 0>(s);
                ryt<0>(s, T[4]);
                acc = fmaf(F, expz0(s), acc);
                break;
            }
            case 3: {  // doublering -> fused embed; 10 tan-RYs; pruned tail
                float s[16];
                embed(s, trigfuse(px[c][0], WU[0]), trigfuse(px[c][1], WU[1]),
                         trigfuse(px[c][2], WU[2]), trigfuse(px[c][3], WU[3]));
                cx<0, 1>(s); cx<1, 2>(s); cx<2, 3>(s); cx<3, 0>(s);
                ryt<0>(s, T[4]); ryt<1>(s, T[5]); ryt<2>(s, T[6]); ryt<3>(s, T[7]);
                cx<3, 0>(s); cx<2, 3>(s); cx<1, 2>(s); cx<0, 1>(s);
                ryt<0>(s, T[8]); ryt<1>(s, T[9]); ryt<2>(s, T[10]); ryt<3>(s, T[11]);
                cx<0, 1>(s); cx<1, 2>(s); cx<2, 3>(s); cx<3, 0>(s);
                ryt<0>(s, T[12]);   // ry1(w13), ry2(w14) pruned
                ryt<3>(s, T[15]);
                cx<3, 0>(s);        // trailing cx23,cx12,cx01 pruned
                acc = fmaf(F, expz0(s), acc);
                break;
            }
            default: {  // blockring -> fused embed; 8 tan-RYs
                float s[16];
                embed(s, trigfuse(px[c][0], WU[0]), trigfuse(px[c][1], WU[1]),
                         trigfuse(px[c][2], WU[2]), trigfuse(px[c][3], WU[3]));
                cx<0, 1>(s); cx<2, 3>(s); cx<1, 2>(s); cx<3, 0>(s);
                ryt<0>(s, T[4]); ryt<1>(s, T[5]); ryt<2>(s, T[6]); ryt<3>(s, T[7]);
                cx<0, 1>(s); cx<2, 3>(s); cx<1, 2>(s); cx<3, 0>(s);
                ryt<0>(s, T[8]); ryt<1>(s, T[9]); ryt<2>(s, T[10]); ryt<3>(s, T[11]);
                cx<0, 1>(s); cx<2, 3>(s); cx<1, 2>(s); cx<3, 0>(s);
                acc = fmaf(F, expz0(s), acc);
                break;
            }
        }
    }

    out[((b * 16 + o) * HP + h) * WP + w] = acc;
}

extern "C" void kernel_launch(void* const* d_in, const int* in_sizes, int n_in,
                              void* d_out, int out_size) {
    const float* in = (const float*)d_in[0];   // (16,3,32,32)
    const float* w  = (const float*)d_in[1];   // (16,3,16)
    float* out = (float*)d_out;                // (16,16,31,31)

    dim3 grid((NPOS + 127) / 128, 16);         // 121 x 16 blocks, ONE kernel
    quanv_kernel<<<grid, 128>>>(in, w, out);
}